// round 5
// baseline (speedup 1.0000x reference)
#include <cuda_runtime.h>
#include <math.h>
#include <float.h>

// Problem constants
#define B_ 8
#define T_ 512
#define D_ 256
#define S_ 64
#define P_ 1024
#define R_ 12
#define N1 (R_ * D_)   // 3072: columns of GEMM1 output, n = r*256 + e

// Scratch (device globals — no allocation allowed)
__device__ float g_pooled[B_ * S_ * D_];        // [bs][d]        512 KB
__device__ float g_L[B_ * S_ * 2 * R_];         // [bs][h*12+r]   48 KB
__device__ float g_T1[B_ * S_ * N1];            // [bs][r*256+e]  6.3 MB
__device__ float g_G[B_ * R_ * S_ * S_];        // [(b*12+r)][s][t] 1.6 MB

// ---------------------------------------------------------------------------
// Kernel 1: ragged span max-pool + per-span linear terms.
// grid = B*S blocks, 256 threads (thread = feature d).
// ---------------------------------------------------------------------------
__global__ __launch_bounds__(256)
void pool_kernel(const float* __restrict__ enc,
                 const float* __restrict__ Wl,   // [2D, R] row-major
                 const int* __restrict__ starts,
                 const int* __restrict__ lens) {
    int bs  = blockIdx.x;          // b*64 + s
    int b   = bs >> 6;
    int tid = threadIdx.x;

    int st = starts[bs];
    int en = st + lens[bs] + 1;    // exclusive, >= st+1
    if (en > T_) en = T_;

    const float* p = enc + ((size_t)b * T_ + st) * D_ + tid;
    float m = -FLT_MAX;
    for (int t = st; t < en; ++t) { m = fmaxf(m, *p); p += D_; }
    g_pooled[bs * D_ + tid] = m;

    __shared__ float sp[D_];
    sp[tid] = m;
    __syncthreads();

    // 24 outputs: o = h*12 + r.  L1 (h=0) pairs with head via W[0:D],
    // L2 (h=1) pairs with tail via W[D:2D].
    int warp = tid >> 5, lane = tid & 31;
#pragma unroll
    for (int j = 0; j < 3; ++j) {
        int o = warp * 3 + j;          // 0..23
        int h = o / R_;
        int r = o - h * R_;
        float sum = 0.f;
        for (int d = lane; d < D_; d += 32)
            sum += sp[d] * Wl[(h * D_ + d) * R_ + r];
#pragma unroll
        for (int off = 16; off; off >>= 1)
            sum += __shfl_xor_sync(0xffffffffu, sum, off);
        if (lane == 0) g_L[bs * (2 * R_) + o] = sum;
    }
}

// ---------------------------------------------------------------------------
// Kernel 2: GEMM1  T1[(b,s), (r,e)] = sum_d pooled[(b,s), d] * Wb[r, d, e]
// A: 512x256 row-major, "B": for column n = r*256+e, element(k,n) at
//    Wb[r*65536 + k*256 + e].  A 64-col tile never crosses an r boundary.
// BM=BN=64, BK=32, 256 threads, 4x4 micro-tile.
// ---------------------------------------------------------------------------
__global__ __launch_bounds__(256)
void gemm1_kernel(const float* __restrict__ Wb) {
    __shared__ float As[32][64];   // [k][m] (transposed for float4 reads)
    __shared__ float Bs[32][64];   // [k][n]

    int tid = threadIdx.x;
    int m0 = blockIdx.y * 64;
    int n0 = blockIdx.x * 64;
    int r  = n0 >> 8;
    int e0 = n0 & 255;
    const float* Bbase = Wb + (size_t)r * (D_ * D_) + e0;
    const float* A = g_pooled;

    int ty = tid >> 4, tx = tid & 15;          // 16x16 thread grid
    int ar = tid >> 3, ac = tid & 7;           // A loads: 32 rows/pass, 8 f4 cols
    int br = tid >> 4, bc = tid & 15;          // B loads: 16 rows/pass, 16 f4 cols

    float acc[4][4] = {};

    for (int k0 = 0; k0 < D_; k0 += 32) {
#pragma unroll
        for (int i = 0; i < 2; ++i) {
            int row = ar + i * 32;
            float4 v = *(const float4*)(A + (m0 + row) * D_ + k0 + ac * 4);
            As[ac * 4 + 0][row] = v.x;
            As[ac * 4 + 1][row] = v.y;
            As[ac * 4 + 2][row] = v.z;
            As[ac * 4 + 3][row] = v.w;
        }
#pragma unroll
        for (int i = 0; i < 2; ++i) {
            int row = br + i * 16;
            float4 v = *(const float4*)(Bbase + (size_t)(k0 + row) * D_ + bc * 4);
            *(float4*)&Bs[row][bc * 4] = v;
        }
        __syncthreads();

#pragma unroll
        for (int kk = 0; kk < 32; ++kk) {
            float4 a = *(float4*)&As[kk][ty * 4];
            float4 b = *(float4*)&Bs[kk][tx * 4];
            float av[4] = {a.x, a.y, a.z, a.w};
            float bv[4] = {b.x, b.y, b.z, b.w};
#pragma unroll
            for (int i = 0; i < 4; ++i)
#pragma unroll
                for (int j = 0; j < 4; ++j)
                    acc[i][j] += av[i] * bv[j];
        }
        __syncthreads();
    }

#pragma unroll
    for (int i = 0; i < 4; ++i) {
        float4 v = make_float4(acc[i][0], acc[i][1], acc[i][2], acc[i][3]);
        *(float4*)(g_T1 + (size_t)(m0 + ty * 4 + i) * N1 + n0 + tx * 4) = v;
    }
}

// ---------------------------------------------------------------------------
// Kernel 3: GEMM2 (batched NT)  G[b,r,s,t] = sum_e T1[b,s,r*256+e] * pooled[b,t,e]
// One block per (b,r): 64x64x256, 256 threads, 4x4 micro-tile, 64-wide k chunks.
// ---------------------------------------------------------------------------
__global__ __launch_bounds__(256)
void gemm2_kernel() {
    int bid = blockIdx.x;                 // b*12 + r
    int b = bid / R_;
    int r = bid - b * R_;

    __shared__ float As[64][64];          // [e][s]
    __shared__ float Bs[64][64];          // [e][t]

    int tid = threadIdx.x;
    int ty = tid >> 4, tx = tid & 15;
    int lr = tid >> 2;                    // row 0..63
    int lc = tid & 3;                     // base float4 col group

    const float* Abase = g_T1 + (size_t)b * S_ * N1 + r * D_;   // row s: +s*N1
    const float* Bbase = g_pooled + (size_t)b * S_ * D_;        // row t: +t*256

    float acc[4][4] = {};

    for (int e0 = 0; e0 < D_; e0 += 64) {
#pragma unroll
        for (int i = 0; i < 4; ++i) {
            int cg = lc + 4 * i;          // 0..15
            float4 v = *(const float4*)(Abase + (size_t)lr * N1 + e0 + cg * 4);
            As[cg * 4 + 0][lr] = v.x;
            As[cg * 4 + 1][lr] = v.y;
            As[cg * 4 + 2][lr] = v.z;
            As[cg * 4 + 3][lr] = v.w;
            float4 w = *(const float4*)(Bbase + lr * D_ + e0 + cg * 4);
            Bs[cg * 4 + 0][lr] = w.x;
            Bs[cg * 4 + 1][lr] = w.y;
            Bs[cg * 4 + 2][lr] = w.z;
            Bs[cg * 4 + 3][lr] = w.w;
        }
        __syncthreads();

#pragma unroll
        for (int kk = 0; kk < 64; ++kk) {
            float4 a = *(float4*)&As[kk][ty * 4];
            float4 bv = *(float4*)&Bs[kk][tx * 4];
            float av[4] = {a.x, a.y, a.z, a.w};
            float bw[4] = {bv.x, bv.y, bv.z, bv.w};
#pragma unroll
            for (int i = 0; i < 4; ++i)
#pragma unroll
                for (int j = 0; j < 4; ++j)
                    acc[i][j] += av[i] * bw[j];
        }
        __syncthreads();
    }

#pragma unroll
    for (int i = 0; i < 4; ++i) {
        float4 v = make_float4(acc[i][0], acc[i][1], acc[i][2], acc[i][3]);
        *(float4*)(g_G + (size_t)bid * (S_ * S_) + (ty * 4 + i) * S_ + tx * 4) = v;
    }
}

// ---------------------------------------------------------------------------
// Kernel 4: final pair scores + sigmoid.  One thread per (b,p,r).
// ---------------------------------------------------------------------------
__global__ __launch_bounds__(256)
void score_kernel(const float* __restrict__ bias,
                  const int* __restrict__ ph,
                  const int* __restrict__ pt,
                  float* __restrict__ out) {
    int g = blockIdx.x * blockDim.x + threadIdx.x;
    if (g >= B_ * P_ * R_) return;
    int r  = g % R_;
    int bp = g / R_;          // b*1024 + p
    int b  = bp >> 10;

    int h = ph[bp];
    int t = pt[bp];

    float sc = g_L[(b * S_ + h) * (2 * R_) + r]
             + g_L[(b * S_ + t) * (2 * R_) + R_ + r]
             + bias[r]
             + g_G[(((size_t)b * R_ + r) * S_ + h) * S_ + t];
    out[g] = 1.f / (1.f + expf(-sc));
}

// ---------------------------------------------------------------------------
// Launch.  Inputs in metadata order (setup_inputs dict order):
// 0 encoded f32 [8,512,256]   1 W_linear f32 [512,12]   2 b_linear f32 [12]
// 3 W_bilinear f32 [12,256,256]
// 4 span_starts i32 [8,64]    5 span_lens i32 [8,64]
// 6 pair_head i32 [8,1024]    7 pair_tail i32 [8,1024]
// Output f32 [8,1024,12].
// ---------------------------------------------------------------------------
extern "C" void kernel_launch(void* const* d_in, const int* in_sizes, int n_in,
                              void* d_out, int out_size) {
    const float* enc = (const float*)d_in[0];
    const float* Wl  = (const float*)d_in[1];
    const float* bl  = (const float*)d_in[2];
    const float* Wb  = (const float*)d_in[3];
    const int* sst   = (const int*)d_in[4];
    const int* sln   = (const int*)d_in[5];
    const int* ph    = (const int*)d_in[6];
    const int* pt    = (const int*)d_in[7];
    float* out = (float*)d_out;

    pool_kernel<<<B_ * S_, 256>>>(enc, Wl, sst, sln);
    gemm1_kernel<<<dim3(N1 / 64, (B_ * S_) / 64), 256>>>(Wb);
    gemm2_kernel<<<B_ * R_, 256>>>();
    score_kernel<<<(B_ * P_ * R_ + 255) / 256, 256>>>(bl, ph, pt, out);
}